// round 15
// baseline (speedup 1.0000x reference)
#include <cuda_runtime.h>

#define NBINS    10
#define NSLOTS   11          // 10 real bins + 1 dead slot (g >= 1)
#define NT       256
#define GRID_MAX 1280        // upper bound for partials array (>= 8 * numSMs)

// Per-block partials: every block overwrites its own slot -> no zeroing pass.
__device__ float2   g_part[GRID_MAX][NBINS];
__device__ unsigned g_ticket;   // zero-init at load; last block resets each call

__device__ __forceinline__ void ghmc_acc(float p, float t, float2* __restrict__ h) {
    // slot = min(floor(10*|p-t|), 10); slot 10 is dead (discarded later).
    float g10 = fabsf(p - t) * 10.0f;
    int  slot = min((int)g10, NSLOTS - 1);

    // bce = t*p - softplus(p);  softplus(p) = max(p,0) + log(1+exp(-|p|))
    float e   = __expf(-fabsf(p));
    float l   = __logf(1.0f + e);
    float bce = t * p - fmaxf(p, 0.0f) - l;

    float2 a = h[slot * NT];   // stride NT*8B: conflict-free across lanes
    a.x += bce;
    a.y += 1.0f;
    h[slot * NT] = a;
}

__device__ __forceinline__ void ghmc_acc2(float2 p, float2 t,
                                          float2* __restrict__ h) {
    ghmc_acc(p.x, t.x, h);
    ghmc_acc(p.y, t.y, h);
}

__global__ __launch_bounds__(NT) void ghmc_kernel(
    const float2* __restrict__ pred,
    const float2* __restrict__ targ,
    int n2, int full_iters,
    float* __restrict__ out) {
    __shared__ float2 hist[NSLOTS * NT];   // 22,528 B -> 8 CTAs/SM (proven)
    __shared__ float  s_s[NBINS], s_c[NBINS];
    __shared__ bool   s_last;

    const int tid     = threadIdx.x;
    const int tstride = gridDim.x * NT;    // uniform; grid sized to 8*numSMs

    #pragma unroll
    for (int i = 0; i < NSLOTS; i++)
        hist[i * NT + tid] = make_float2(0.0f, 0.0f);
    __syncthreads();

    float2* h = &hist[tid];

    int i = blockIdx.x * NT + tid;

    // 8 front-batched, coalesced LDG.64 per iter (same 64 B / 16 L1 wavefronts
    // as 4x LDG.128, but MLP = 8 outstanding loads per warp at equal regs).
    for (int k = 0; k < full_iters; k++) {
        float2 pa = pred[i];
        float2 pb = pred[i + tstride];
        float2 pc = pred[i + 2 * tstride];
        float2 pd = pred[i + 3 * tstride];
        float2 ta = targ[i];
        float2 tb = targ[i + tstride];
        float2 tc = targ[i + 2 * tstride];
        float2 td = targ[i + 3 * tstride];
        ghmc_acc2(pa, ta, h);
        ghmc_acc2(pb, tb, h);
        ghmc_acc2(pc, tc, h);
        ghmc_acc2(pd, td, h);
        i += 4 * tstride;
    }
    // Remainder: plain grid-stride, still coalesced.
    for (; i < n2; i += tstride) {
        float2 p = pred[i];
        float2 t = targ[i];
        ghmc_acc2(p, t, h);
    }
    __syncthreads();

    // ---- block reduction: 16 threads per bin, each sums 16 columns ----
    if (tid < NBINS * 16) {
        int bin = tid >> 4;
        int j   = tid & 15;
        float sx = 0.0f, sy = 0.0f;
        #pragma unroll
        for (int k = 0; k < NT / 16; k++) {
            float2 a = hist[bin * NT + j + k * 16];
            sx += a.x;
            sy += a.y;
        }
        #pragma unroll
        for (int o = 8; o > 0; o >>= 1) {
            sx += __shfl_down_sync(0xffffffffu, sx, o, 16);
            sy += __shfl_down_sync(0xffffffffu, sy, o, 16);
        }
        if (j == 0)
            g_part[blockIdx.x][bin] = make_float2(sx, sy);
    }

    // ---- last-block final reduction (fused finalize) ----
    __threadfence();
    __syncthreads();
    if (tid == 0) {
        unsigned t = atomicAdd(&g_ticket, 1u);
        s_last = (t == gridDim.x - 1);
    }
    __syncthreads();
    if (!s_last) return;

    __threadfence();
    if (tid < NBINS * 16) {
        int bin = tid >> 4;
        int j   = tid & 15;
        float sx = 0.0f, sy = 0.0f;
        for (int b = j; b < (int)gridDim.x; b += 16) {   // L2-hot partials
            float2 a = g_part[b][bin];
            sx += a.x;
            sy += a.y;
        }
        #pragma unroll
        for (int o = 8; o > 0; o >>= 1) {
            sx += __shfl_down_sync(0xffffffffu, sx, o, 16);
            sy += __shfl_down_sync(0xffffffffu, sy, o, 16);
        }
        if (j == 0) { s_s[bin] = sx; s_c[bin] = sy; }
    }
    __syncthreads();
    if (tid == 0) {
        float n = 0.0f, acc = 0.0f;
        #pragma unroll
        for (int i2 = 0; i2 < NBINS; i2++) {
            if (s_c[i2] > 0.0f) {
                n   += 1.0f;
                acc += s_s[i2] / s_c[i2];
            }
        }
        out[0] = -acc / fmaxf(n, 1.0f);
        g_ticket = 0;   // reset for next graph replay
    }
}

extern "C" void kernel_launch(void* const* d_in, const int* in_sizes, int n_in,
                              void* d_out, int out_size) {
    const float2* pred = (const float2*)d_in[0];
    const float2* targ = (const float2*)d_in[1];
    float* out = (float*)d_out;
    int n  = in_sizes[0];
    int n2 = n >> 1;                          // n divisible by 2

    // Exactly one resident wave: 8 CTAs per actual SM (152 confirmed in R14).
    int dev = 0, nsm = 0;
    cudaGetDevice(&dev);
    cudaDeviceGetAttribute(&nsm, cudaDevAttrMultiProcessorCount, dev);
    if (nsm <= 0 || 8 * nsm > GRID_MAX) nsm = 152;   // fallback
    int grid = 8 * nsm;

    int tstride    = grid * NT;
    int full_iters = n2 / (4 * tstride);      // unrolled main-loop trip count

    ghmc_kernel<<<grid, NT>>>(pred, targ, n2, full_iters, out);
}

// round 16
// speedup vs baseline: 1.0486x; 1.0486x over previous
#include <cuda_runtime.h>

#define NBINS    10
#define NSLOTS   11          // 10 real bins + 1 dead slot (g >= 1 or invalid)
#define NT       256
#define GRID_MAX 1280        // upper bound for partials array (>= 8 * numSMs)

// Per-block partials: every block overwrites its own slot -> no zeroing pass.
__device__ float2   g_part[GRID_MAX][NBINS];
__device__ unsigned g_ticket;   // zero-init at load; last block resets each call

__device__ __forceinline__ void ghmc_acc_slot(int slot, float p, float t,
                                              float2* __restrict__ h) {
    // bce = t*p - softplus(p);  softplus(p) = max(p,0) + log(1+exp(-|p|))
    float e   = __expf(-fabsf(p));
    float l   = __logf(1.0f + e);
    float bce = t * p - fmaxf(p, 0.0f) - l;

    float2 a = h[slot * NT];   // stride NT*8B: conflict-free across lanes
    a.x += bce;
    a.y += 1.0f;
    h[slot * NT] = a;
}

__device__ __forceinline__ void ghmc_acc(float p, float t, float2* __restrict__ h) {
    // slot = min(floor(10*|p-t|), 10); slot 10 is dead (discarded later).
    float g10 = fabsf(p - t) * 10.0f;
    int  slot = min((int)g10, NSLOTS - 1);
    ghmc_acc_slot(slot, p, t, h);
}

__device__ __forceinline__ void ghmc_acc4(float4 p, float4 t,
                                          float2* __restrict__ h) {
    ghmc_acc(p.x, t.x, h);
    ghmc_acc(p.y, t.y, h);
    ghmc_acc(p.z, t.z, h);
    ghmc_acc(p.w, t.w, h);
}

// Guarded variant: invalid elements route to the dead slot (10).
__device__ __forceinline__ void ghmc_acc4g(float4 p, float4 t, bool v,
                                           float2* __restrict__ h) {
    {
        float g10 = fabsf(p.x - t.x) * 10.0f;
        int slot = v ? min((int)g10, NSLOTS - 1) : (NSLOTS - 1);
        ghmc_acc_slot(slot, p.x, t.x, h);
    }
    {
        float g10 = fabsf(p.y - t.y) * 10.0f;
        int slot = v ? min((int)g10, NSLOTS - 1) : (NSLOTS - 1);
        ghmc_acc_slot(slot, p.y, t.y, h);
    }
    {
        float g10 = fabsf(p.z - t.z) * 10.0f;
        int slot = v ? min((int)g10, NSLOTS - 1) : (NSLOTS - 1);
        ghmc_acc_slot(slot, p.z, t.z, h);
    }
    {
        float g10 = fabsf(p.w - t.w) * 10.0f;
        int slot = v ? min((int)g10, NSLOTS - 1) : (NSLOTS - 1);
        ghmc_acc_slot(slot, p.w, t.w, h);
    }
}

__global__ __launch_bounds__(NT) void ghmc_kernel(
    const float4* __restrict__ pred,
    const float4* __restrict__ targ,
    int n4, int full_iters,
    float* __restrict__ out) {
    __shared__ float2 hist[NSLOTS * NT];   // 22,528 B -> 8 CTAs/SM (proven)
    __shared__ float  s_s[NBINS], s_c[NBINS];
    __shared__ bool   s_last;

    const int tid     = threadIdx.x;
    const int tstride = gridDim.x * NT;    // uniform; grid sized to 8*numSMs

    #pragma unroll
    for (int i = 0; i < NSLOTS; i++)
        hist[i * NT + tid] = make_float2(0.0f, 0.0f);
    __syncthreads();

    float2* h = &hist[tid];

    int i = blockIdx.x * NT + tid;

    // Steady state: 4 coalesced LDG.128 front-batched per iter.
    for (int k = 0; k < full_iters; k++) {
        float4 pa = pred[i];
        float4 pb = pred[i + tstride];
        float4 ta = targ[i];
        float4 tb = targ[i + tstride];
        ghmc_acc4(pa, ta, h);
        ghmc_acc4(pb, tb, h);
        i += 2 * tstride;
    }

    // Peeled guarded tail: one more main-shaped iteration with bounds
    // predicates (remainder < 2*tstride). Keeps MLP=4 in the tail; invalid
    // elements land in the dead slot.
    {
        bool va = (i < n4);
        bool vb = (i + tstride < n4);
        float4 z  = make_float4(0.f, 0.f, 0.f, 0.f);
        float4 pa = va ? pred[i] : z;
        float4 pb = vb ? pred[i + tstride] : z;
        float4 ta = va ? targ[i] : z;
        float4 tb = vb ? targ[i + tstride] : z;
        ghmc_acc4g(pa, ta, va, h);
        ghmc_acc4g(pb, tb, vb, h);
    }
    __syncthreads();

    // ---- block reduction: 16 threads per bin, each sums 16 columns ----
    if (tid < NBINS * 16) {
        int bin = tid >> 4;
        int j   = tid & 15;
        float sx = 0.0f, sy = 0.0f;
        #pragma unroll
        for (int k = 0; k < NT / 16; k++) {
            float2 a = hist[bin * NT + j + k * 16];
            sx += a.x;
            sy += a.y;
        }
        #pragma unroll
        for (int o = 8; o > 0; o >>= 1) {
            sx += __shfl_down_sync(0xffffffffu, sx, o, 16);
            sy += __shfl_down_sync(0xffffffffu, sy, o, 16);
        }
        if (j == 0)
            g_part[blockIdx.x][bin] = make_float2(sx, sy);
    }

    // ---- last-block final reduction (fused finalize) ----
    __threadfence();
    __syncthreads();
    if (tid == 0) {
        unsigned t = atomicAdd(&g_ticket, 1u);
        s_last = (t == gridDim.x - 1);
    }
    __syncthreads();
    if (!s_last) return;

    __threadfence();
    if (tid < NBINS * 16) {
        int bin = tid >> 4;
        int j   = tid & 15;
        float sx = 0.0f, sy = 0.0f;
        for (int b = j; b < (int)gridDim.x; b += 16) {   // L2-hot partials
            float2 a = g_part[b][bin];
            sx += a.x;
            sy += a.y;
        }
        #pragma unroll
        for (int o = 8; o > 0; o >>= 1) {
            sx += __shfl_down_sync(0xffffffffu, sx, o, 16);
            sy += __shfl_down_sync(0xffffffffu, sy, o, 16);
        }
        if (j == 0) { s_s[bin] = sx; s_c[bin] = sy; }
    }
    __syncthreads();
    if (tid == 0) {
        float n = 0.0f, acc = 0.0f;
        #pragma unroll
        for (int i2 = 0; i2 < NBINS; i2++) {
            if (s_c[i2] > 0.0f) {
                n   += 1.0f;
                acc += s_s[i2] / s_c[i2];
            }
        }
        out[0] = -acc / fmaxf(n, 1.0f);
        g_ticket = 0;   // reset for next graph replay
    }
}

extern "C" void kernel_launch(void* const* d_in, const int* in_sizes, int n_in,
                              void* d_out, int out_size) {
    const float4* pred = (const float4*)d_in[0];
    const float4* targ = (const float4*)d_in[1];
    float* out = (float*)d_out;
    int n  = in_sizes[0];
    int n4 = n >> 2;                          // n divisible by 4

    // Exactly one resident wave: 8 CTAs per actual SM (152 confirmed in R14).
    int dev = 0, nsm = 0;
    cudaGetDevice(&dev);
    cudaDeviceGetAttribute(&nsm, cudaDevAttrMultiProcessorCount, dev);
    if (nsm <= 0 || 8 * nsm > GRID_MAX) nsm = 152;   // fallback
    int grid = 8 * nsm;

    int tstride    = grid * NT;
    int full_iters = n4 / (2 * tstride);      // peeled guarded iter covers rest

    ghmc_kernel<<<grid, NT>>>(pred, targ, n4, full_iters, out);
}